// round 3
// baseline (speedup 1.0000x reference)
#include <cuda_runtime.h>
#include <cstdint>

// Problem constants (fixed by the reference)
#define BB   64
#define MM   2048
#define NN   2048
#define KK   64           // K in logical int8 elements
#define KWRD 16           // K in packed 32-bit words (dp4a granularity)

#define TILE    128       // CTA tile: 128x128 outputs
#define THREADS 256       // 16x16 threads, 8x8 micro-tile each

// 1 if the harness promoted int8 inputs to int32 (one int32 per element)
__device__ int g_inputs_are_i32;

// ---------------------------------------------------------------------------
// Probe: if inputs are int32-promoted int8 values, every 32-bit word is a
// sign-extended small integer: bytes 1..3 are 0x00 (v>=0) or 0xFF (v<0).
// Genuine packed int8 random data matches this for 2048 consecutive words
// with probability ~0.
// ---------------------------------------------------------------------------
__global__ void probe_dtype_kernel(const uint32_t* __restrict__ a)
{
    if (threadIdx.x != 0 || blockIdx.x != 0) return;
    int is_i32 = 1;
    for (int i = 0; i < 2048; i++) {
        uint32_t v  = a[i];
        uint32_t hi = v >> 8;
        uint32_t expect = ((v & 0x80u) != 0) ? 0x00FFFFFFu : 0x00000000u;
        if (hi != expect) { is_i32 = 0; break; }
    }
    g_inputs_are_i32 = is_i32;
}

__device__ __forceinline__ uint32_t pack4(int4 v)
{
    return (uint32_t)(v.x & 0xff)
         | ((uint32_t)(v.y & 0xff) << 8)
         | ((uint32_t)(v.z & 0xff) << 16)
         | ((uint32_t)(v.w)        << 24);
}

__global__ __launch_bounds__(THREADS, 2)
void bmm_s8t_s8n_f32_kernel(const void* __restrict__ A,
                            const void* __restrict__ B,
                            const float* __restrict__ alpha_p,
                            float*       __restrict__ out)
{
    // K-transposed smem: [kword][row] so fragment loads are contiguous LDS.128
    __shared__ uint32_t As[KWRD][TILE];
    __shared__ uint32_t Bs[KWRD][TILE];

    const int bz     = blockIdx.z;
    const int tile_m = blockIdx.y * TILE;
    const int tile_n = blockIdx.x * TILE;
    const int tid    = threadIdx.x;

    const int lm = tid & (TILE - 1);   // row within tile: 0..127
    const int q0 = tid >> 7;           // 0 or 1

    const int is_i32 = g_inputs_are_i32;

    if (is_i32) {
        // ---- int32-promoted path: 4 promoted elements -> 1 dp4a word ----
        const int4* __restrict__ Ag = reinterpret_cast<const int4*>(
            (const int*)A + (size_t)bz * MM * KK + (size_t)(tile_m + lm) * KK);
        const int4* __restrict__ Bg = reinterpret_cast<const int4*>(
            (const int*)B + (size_t)bz * NN * KK + (size_t)(tile_n + lm) * KK);
        #pragma unroll
        for (int p = 0; p < 2; p++) {
            const int q = q0 + 2 * p;      // word-group 0..3
            #pragma unroll
            for (int j = 0; j < 4; j++) {
                const int kw = q * 4 + j;
                As[kw][lm] = pack4(Ag[kw]);
                Bs[kw][lm] = pack4(Bg[kw]);
            }
        }
    } else {
        // ---- genuine packed int8 path ----
        const uint32_t* __restrict__ Ag = reinterpret_cast<const uint32_t*>(
            (const int8_t*)A + (size_t)bz * MM * KK + (size_t)tile_m * KK);
        const uint32_t* __restrict__ Bg = reinterpret_cast<const uint32_t*>(
            (const int8_t*)B + (size_t)bz * NN * KK + (size_t)tile_n * KK);
        #pragma unroll
        for (int p = 0; p < 2; p++) {
            const int q = q0 + 2 * p;
            uint4 va = reinterpret_cast<const uint4*>(Ag + (size_t)lm * KWRD)[q];
            As[q * 4 + 0][lm] = va.x;
            As[q * 4 + 1][lm] = va.y;
            As[q * 4 + 2][lm] = va.z;
            As[q * 4 + 3][lm] = va.w;
            uint4 vb = reinterpret_cast<const uint4*>(Bg + (size_t)lm * KWRD)[q];
            Bs[q * 4 + 0][lm] = vb.x;
            Bs[q * 4 + 1][lm] = vb.y;
            Bs[q * 4 + 2][lm] = vb.z;
            Bs[q * 4 + 3][lm] = vb.w;
        }
    }
    __syncthreads();

    // ---- Register micro-tile 8x8 ----
    const int tx = tid & 15;       // n direction
    const int ty = tid >> 4;       // m direction
    const int m0 = ty * 8;
    const int n0 = tx * 8;

    int acc[8][8];
    #pragma unroll
    for (int i = 0; i < 8; i++)
        #pragma unroll
        for (int j = 0; j < 8; j++)
            acc[i][j] = 0;

    #pragma unroll
    for (int kw = 0; kw < KWRD; kw++) {
        uint32_t a[8], b[8];
        *reinterpret_cast<uint4*>(&a[0]) = *reinterpret_cast<const uint4*>(&As[kw][m0]);
        *reinterpret_cast<uint4*>(&a[4]) = *reinterpret_cast<const uint4*>(&As[kw][m0 + 4]);
        *reinterpret_cast<uint4*>(&b[0]) = *reinterpret_cast<const uint4*>(&Bs[kw][n0]);
        *reinterpret_cast<uint4*>(&b[4]) = *reinterpret_cast<const uint4*>(&Bs[kw][n0 + 4]);

        #pragma unroll
        for (int i = 0; i < 8; i++)
            #pragma unroll
            for (int j = 0; j < 8; j++)
                acc[i][j] = __dp4a((int)a[i], (int)b[j], acc[i][j]);
    }

    // ---- Epilogue: alpha * acc -> fp32, vectorized stores ----
    const float alpha = __ldg(alpha_p);

    float* __restrict__ outp =
        out + (size_t)bz * MM * NN + (size_t)(tile_m + m0) * NN + (tile_n + n0);

    #pragma unroll
    for (int i = 0; i < 8; i++) {
        float4 v0, v1;
        v0.x = alpha * (float)acc[i][0];
        v0.y = alpha * (float)acc[i][1];
        v0.z = alpha * (float)acc[i][2];
        v0.w = alpha * (float)acc[i][3];
        v1.x = alpha * (float)acc[i][4];
        v1.y = alpha * (float)acc[i][5];
        v1.z = alpha * (float)acc[i][6];
        v1.w = alpha * (float)acc[i][7];
        float4* row = reinterpret_cast<float4*>(outp + (size_t)i * NN);
        row[0] = v0;
        row[1] = v1;
    }
}

extern "C" void kernel_launch(void* const* d_in, const int* in_sizes, int n_in,
                              void* d_out, int out_size)
{
    // alpha is the unique 1-element input; the two big tensors are a then b.
    int ia = -1, ib = -1, ialpha = -1;
    for (int i = 0; i < n_in; i++) {
        if (in_sizes[i] == 1) {
            if (ialpha < 0) ialpha = i;
        } else if (ia < 0) {
            ia = i;
        } else if (ib < 0) {
            ib = i;
        }
    }
    if (ialpha < 0) ialpha = n_in - 1;   // fallback

    const void*  a     = d_in[ia];
    const void*  b     = d_in[ib];
    const float* alpha = reinterpret_cast<const float*>(d_in[ialpha]);
    float*       out   = reinterpret_cast<float*>(d_out);

    // Probe dtype layout (same stream -> ordered before the GEMM)
    probe_dtype_kernel<<<1, 32>>>(reinterpret_cast<const uint32_t*>(a));

    dim3 grid(NN / TILE, MM / TILE, BB);   // (16, 16, 64)
    dim3 block(THREADS);
    bmm_s8t_s8n_f32_kernel<<<grid, block>>>(a, b, alpha, out);
}

// round 4
// speedup vs baseline: 2.4826x; 2.4826x over previous
#include <cuda_runtime.h>
#include <cstdint>

// Problem constants (fixed by the reference)
#define BB   64
#define MM   2048
#define NN   2048
#define KK   64                      // K in logical int8 elements
#define KW   16                      // K in packed 32-bit words
#define WORDS (BB * MM * KK / 4)     // packed words per tensor = 2,097,152

// 1 if the harness promoted int8 inputs to int32 (one int32 per element)
__device__ int g_inputs_are_i32;

// Packed int8 scratch (static device allocations — allowed)
__device__ uint32_t A_pk[WORDS];     // 8.4 MB
__device__ uint32_t B_pk[WORDS];     // 8.4 MB

__device__ __forceinline__ uint32_t pack4(int4 v)
{
    return (uint32_t)(v.x & 0xff)
         | ((uint32_t)(v.y & 0xff) << 8)
         | ((uint32_t)(v.z & 0xff) << 16)
         | ((uint32_t)(v.w)        << 24);
}

// ---------------------------------------------------------------------------
// Parallel dtype probe: int32-promoted int8 words have bytes 1..3 equal to the
// sign extension of byte 0. Check 2048 words with 256 threads.
// ---------------------------------------------------------------------------
__global__ void probe_dtype_kernel(const uint32_t* __restrict__ a)
{
    int ok = 1;
    #pragma unroll
    for (int r = 0; r < 8; r++) {
        uint32_t v = a[threadIdx.x + r * 256];
        uint32_t hi = v >> 8;
        uint32_t expect = (v & 0x80u) ? 0x00FFFFFFu : 0x00000000u;
        if (hi != expect) ok = 0;
    }
    int all = __syncthreads_and(ok);
    if (threadIdx.x == 0) g_inputs_are_i32 = all;
}

// ---------------------------------------------------------------------------
// Pack: int32-promoted -> packed int8 words (or plain copy if already packed)
// ---------------------------------------------------------------------------
__global__ __launch_bounds__(256)
void pack_kernel(const void* __restrict__ srcA, const void* __restrict__ srcB)
{
    const int i = blockIdx.x * blockDim.x + threadIdx.x;   // word index
    if (i >= WORDS) return;
    if (g_inputs_are_i32) {
        A_pk[i] = pack4(reinterpret_cast<const int4*>(srcA)[i]);
        B_pk[i] = pack4(reinterpret_cast<const int4*>(srcB)[i]);
    } else {
        A_pk[i] = reinterpret_cast<const uint32_t*>(srcA)[i];
        B_pk[i] = reinterpret_cast<const uint32_t*>(srcB)[i];
    }
}

// ---------------------------------------------------------------------------
// Tensor-core GEMM: mma.sync.m16n8k32.s8, CTA 128x128, 8 warps, warp 64x32.
// A [m][k] row-major == .row operand; B [n][k] == .col operand. K=64 = 2 steps.
// ---------------------------------------------------------------------------
__global__ __launch_bounds__(256, 2)
void bmm_mma_kernel(const float* __restrict__ alpha_p, float* __restrict__ out)
{
    const int bz     = blockIdx.z;
    const int tile_m = blockIdx.y * 128;
    const int tile_n = blockIdx.x * 128;

    const int wid  = threadIdx.x >> 5;
    const int lane = threadIdx.x & 31;
    const int g    = lane >> 2;      // row/col group 0..7
    const int t    = lane & 3;       // k-word lane 0..3

    const int wm = wid >> 2;         // 0..1 -> m offset
    const int wn = wid & 3;          // 0..3 -> n offset
    const int m_base = tile_m + wm * 64;
    const int n_base = tile_n + wn * 32;

    const uint32_t* __restrict__ Aw = A_pk + (size_t)bz * MM * KW + (size_t)m_base * KW;
    const uint32_t* __restrict__ Bw = B_pk + (size_t)bz * NN * KW + (size_t)n_base * KW;

    int c[4][4][4] = {};             // [m16 tile][n8 tile][frag reg]

    #pragma unroll
    for (int s = 0; s < 2; s++) {    // k-step: words s*8 .. s*8+7
        uint32_t a[4][4];
        #pragma unroll
        for (int mi = 0; mi < 4; mi++) {
            const int r0 = mi * 16 + g;
            a[mi][0] = Aw[(size_t)r0       * KW + s * 8 + t];
            a[mi][1] = Aw[(size_t)(r0 + 8) * KW + s * 8 + t];
            a[mi][2] = Aw[(size_t)r0       * KW + s * 8 + 4 + t];
            a[mi][3] = Aw[(size_t)(r0 + 8) * KW + s * 8 + 4 + t];
        }
        uint32_t b[4][2];
        #pragma unroll
        for (int nj = 0; nj < 4; nj++) {
            const int col = nj * 8 + g;
            b[nj][0] = Bw[(size_t)col * KW + s * 8 + t];
            b[nj][1] = Bw[(size_t)col * KW + s * 8 + 4 + t];
        }
        #pragma unroll
        for (int mi = 0; mi < 4; mi++)
            #pragma unroll
            for (int nj = 0; nj < 4; nj++)
                asm volatile(
                    "mma.sync.aligned.m16n8k32.row.col.s32.s8.s8.s32 "
                    "{%0,%1,%2,%3}, {%4,%5,%6,%7}, {%8,%9}, {%0,%1,%2,%3};\n"
                    : "+r"(c[mi][nj][0]), "+r"(c[mi][nj][1]),
                      "+r"(c[mi][nj][2]), "+r"(c[mi][nj][3])
                    : "r"(a[mi][0]), "r"(a[mi][1]), "r"(a[mi][2]), "r"(a[mi][3]),
                      "r"(b[nj][0]), "r"(b[nj][1]));
    }

    // Epilogue: alpha * s32 -> f32, float2 stores (c-fragment cols 2t, 2t+1)
    const float alpha = __ldg(alpha_p);
    float* __restrict__ obase = out + (size_t)bz * MM * NN;

    #pragma unroll
    for (int mi = 0; mi < 4; mi++) {
        const int row0 = m_base + mi * 16 + g;
        float* o0 = obase + (size_t)row0 * NN;
        float* o1 = o0 + 8 * NN;
        #pragma unroll
        for (int nj = 0; nj < 4; nj++) {
            const int col = n_base + nj * 8 + 2 * t;
            float2 v0, v1;
            v0.x = alpha * (float)c[mi][nj][0];
            v0.y = alpha * (float)c[mi][nj][1];
            v1.x = alpha * (float)c[mi][nj][2];
            v1.y = alpha * (float)c[mi][nj][3];
            *reinterpret_cast<float2*>(o0 + col) = v0;
            *reinterpret_cast<float2*>(o1 + col) = v1;
        }
    }
}

extern "C" void kernel_launch(void* const* d_in, const int* in_sizes, int n_in,
                              void* d_out, int out_size)
{
    // alpha is the unique 1-element input; the two big tensors are a then b.
    int ia = -1, ib = -1, ialpha = -1;
    for (int i = 0; i < n_in; i++) {
        if (in_sizes[i] == 1) {
            if (ialpha < 0) ialpha = i;
        } else if (ia < 0) {
            ia = i;
        } else if (ib < 0) {
            ib = i;
        }
    }
    if (ialpha < 0) ialpha = n_in - 1;

    const void*  a     = d_in[ia];
    const void*  b     = d_in[ib];
    const float* alpha = reinterpret_cast<const float*>(d_in[ialpha]);
    float*       out   = reinterpret_cast<float*>(d_out);

    // Same stream -> probe, pack, gemm are ordered. All graph-capturable.
    probe_dtype_kernel<<<1, 256>>>(reinterpret_cast<const uint32_t*>(a));
    pack_kernel<<<WORDS / 256, 256>>>(a, b);

    dim3 grid(NN / 128, MM / 128, BB);   // (16, 16, 64)
    bmm_mma_kernel<<<grid, 256>>>(alpha, out);
}

// round 5
// speedup vs baseline: 2.6444x; 1.0652x over previous
#include <cuda_runtime.h>
#include <cstdint>

// Problem constants (fixed by the reference)
#define BB   64
#define MM   2048
#define NN   2048
#define KK   64                      // K in logical int8 elements
#define KW   16                      // K in packed 32-bit words
#define WORDS (BB * MM * KK / 4)     // packed words per tensor = 2,097,152

#define ROWB 20                      // smem row pitch in words (80B, conflict-free for ldmatrix)

// 1 if the harness promoted int8 inputs to int32 (one int32 per element)
__device__ int g_inputs_are_i32;

// Packed int8 scratch (static device arrays — allowed)
__device__ uint32_t A_pk[WORDS];     // 8.4 MB
__device__ uint32_t B_pk[WORDS];     // 8.4 MB

__device__ __forceinline__ uint32_t pack4(int4 v)
{
    return (uint32_t)(v.x & 0xff)
         | ((uint32_t)(v.y & 0xff) << 8)
         | ((uint32_t)(v.z & 0xff) << 16)
         | ((uint32_t)(v.w)        << 24);
}

// ---------------------------------------------------------------------------
// Parallel dtype probe
// ---------------------------------------------------------------------------
__global__ void probe_dtype_kernel(const uint32_t* __restrict__ a)
{
    int ok = 1;
    #pragma unroll
    for (int r = 0; r < 8; r++) {
        uint32_t v = a[threadIdx.x + r * 256];
        uint32_t hi = v >> 8;
        uint32_t expect = (v & 0x80u) ? 0x00FFFFFFu : 0x00000000u;
        if (hi != expect) ok = 0;
    }
    int all = __syncthreads_and(ok);
    if (threadIdx.x == 0) g_inputs_are_i32 = all;
}

// ---------------------------------------------------------------------------
// Pack: int32-promoted -> packed int8 words (or plain copy if already packed)
// ---------------------------------------------------------------------------
__global__ __launch_bounds__(256)
void pack_kernel(const void* __restrict__ srcA, const void* __restrict__ srcB)
{
    const int i = blockIdx.x * blockDim.x + threadIdx.x;   // word index
    if (i >= WORDS) return;
    if (g_inputs_are_i32) {
        A_pk[i] = pack4(reinterpret_cast<const int4*>(srcA)[i]);
        B_pk[i] = pack4(reinterpret_cast<const int4*>(srcB)[i]);
    } else {
        A_pk[i] = reinterpret_cast<const uint32_t*>(srcA)[i];
        B_pk[i] = reinterpret_cast<const uint32_t*>(srcB)[i];
    }
}

// ---------------------------------------------------------------------------
// Tensor-core GEMM: mma.sync.m16n8k32.s8, CTA 128x128, 8 warps, warp 64x32.
// Packed tiles staged in smem (80B row pitch), fragments via ldmatrix.x4.
// ---------------------------------------------------------------------------
__global__ __launch_bounds__(256, 2)
void bmm_mma_kernel(const float* __restrict__ alpha_p, float* __restrict__ out)
{
    __shared__ uint32_t As[128 * ROWB];   // 10.0 KB
    __shared__ uint32_t Bs[128 * ROWB];   // 10.0 KB

    const int bz     = blockIdx.z;
    const int tile_m = blockIdx.y * 128;
    const int tile_n = blockIdx.x * 128;
    const int tid    = threadIdx.x;

    // ---- Global -> shared: 128 rows x 64B per operand, uint4 per thread x2 ----
    {
        const uint32_t* __restrict__ Aw = A_pk + (size_t)bz * MM * KW + (size_t)tile_m * KW;
        const uint32_t* __restrict__ Bw = B_pk + (size_t)bz * NN * KW + (size_t)tile_n * KW;
        #pragma unroll
        for (int p = 0; p < 2; p++) {
            const int idx = tid + p * 256;     // 0..511
            const int row = idx >> 2;
            const int q   = idx & 3;           // 16B chunk within row
            uint4 va = *reinterpret_cast<const uint4*>(Aw + (size_t)row * KW + q * 4);
            uint4 vb = *reinterpret_cast<const uint4*>(Bw + (size_t)row * KW + q * 4);
            *reinterpret_cast<uint4*>(&As[row * ROWB + q * 4]) = va;
            *reinterpret_cast<uint4*>(&Bs[row * ROWB + q * 4]) = vb;
        }
    }
    __syncthreads();

    const int wid  = tid >> 5;
    const int lane = tid & 31;
    const int g    = lane >> 2;      // row/col group 0..7
    const int t    = lane & 3;       // k-word lane 0..3

    const int wm = wid >> 2;         // 0..1 -> m offset (x64)
    const int wn = wid & 3;          // 0..3 -> n offset (x32)

    // ---- ldmatrix lane addresses (byte offsets into smem) ----
    const uint32_t As_u32 = (uint32_t)__cvta_generic_to_shared(As);
    const uint32_t Bs_u32 = (uint32_t)__cvta_generic_to_shared(Bs);

    // A x4: matrices {rows r0..r0+7 | k0}, {+8 | k0}, {r0.. | k0+16B}, {+8 | k0+16B}
    const int arow = ((lane >> 3) & 1) * 8 + (lane & 7);
    const int akof = (lane >> 4) * 16;
    uint32_t a_addr[4];
    #pragma unroll
    for (int mi = 0; mi < 4; mi++)
        a_addr[mi] = As_u32 + (uint32_t)((wm * 64 + mi * 16 + arow) * (ROWB * 4) + akof);

    // B x4: matrices {cols c0..c0+7 | k0}, {c0 | k0+16B}, {c0+8 | k0}, {c0+8 | k0+16B}
    const int brow = ((lane >> 4) & 1) * 8 + (lane & 7);
    const int bkof = ((lane >> 3) & 1) * 16;
    uint32_t b_addr[2];
    #pragma unroll
    for (int p = 0; p < 2; p++)
        b_addr[p] = Bs_u32 + (uint32_t)((wn * 32 + p * 16 + brow) * (ROWB * 4) + bkof);

    int c[4][4][4] = {};             // [m16 tile][n8 tile][frag reg]

    #pragma unroll
    for (int s = 0; s < 2; s++) {    // k-step: bytes s*32 .. s*32+31
        uint32_t a[4][4];
        #pragma unroll
        for (int mi = 0; mi < 4; mi++)
            asm volatile("ldmatrix.sync.aligned.m8n8.x4.shared.b16 {%0,%1,%2,%3}, [%4];\n"
                         : "=r"(a[mi][0]), "=r"(a[mi][1]), "=r"(a[mi][2]), "=r"(a[mi][3])
                         : "r"(a_addr[mi] + s * 32));

        uint32_t b[4][2];            // [nj][reg]
        #pragma unroll
        for (int p = 0; p < 2; p++)
            asm volatile("ldmatrix.sync.aligned.m8n8.x4.shared.b16 {%0,%1,%2,%3}, [%4];\n"
                         : "=r"(b[2 * p][0]), "=r"(b[2 * p][1]),
                           "=r"(b[2 * p + 1][0]), "=r"(b[2 * p + 1][1])
                         : "r"(b_addr[p] + s * 32));

        #pragma unroll
        for (int mi = 0; mi < 4; mi++)
            #pragma unroll
            for (int nj = 0; nj < 4; nj++)
                asm volatile(
                    "mma.sync.aligned.m16n8k32.row.col.s32.s8.s8.s32 "
                    "{%0,%1,%2,%3}, {%4,%5,%6,%7}, {%8,%9}, {%0,%1,%2,%3};\n"
                    : "+r"(c[mi][nj][0]), "+r"(c[mi][nj][1]),
                      "+r"(c[mi][nj][2]), "+r"(c[mi][nj][3])
                    : "r"(a[mi][0]), "r"(a[mi][1]), "r"(a[mi][2]), "r"(a[mi][3]),
                      "r"(b[nj][0]), "r"(b[nj][1]));
    }

    // ---- Epilogue: alpha * s32 -> f32, float2 stores ----
    const float alpha = __ldg(alpha_p);
    const int m_base = tile_m + wm * 64;
    const int n_base = tile_n + wn * 32;
    float* __restrict__ obase = out + (size_t)bz * MM * NN;

    #pragma unroll
    for (int mi = 0; mi < 4; mi++) {
        const int row0 = m_base + mi * 16 + g;
        float* o0 = obase + (size_t)row0 * NN;
        float* o1 = o0 + 8 * NN;
        #pragma unroll
        for (int nj = 0; nj < 4; nj++) {
            const int col = n_base + nj * 8 + 2 * t;
            float2 v0, v1;
            v0.x = alpha * (float)c[mi][nj][0];
            v0.y = alpha * (float)c[mi][nj][1];
            v1.x = alpha * (float)c[mi][nj][2];
            v1.y = alpha * (float)c[mi][nj][3];
            *reinterpret_cast<float2*>(o0 + col) = v0;
            *reinterpret_cast<float2*>(o1 + col) = v1;
        }
    }
}

extern "C" void kernel_launch(void* const* d_in, const int* in_sizes, int n_in,
                              void* d_out, int out_size)
{
    // alpha is the unique 1-element input; the two big tensors are a then b.
    int ia = -1, ib = -1, ialpha = -1;
    for (int i = 0; i < n_in; i++) {
        if (in_sizes[i] == 1) {
            if (ialpha < 0) ialpha = i;
        } else if (ia < 0) {
            ia = i;
        } else if (ib < 0) {
            ib = i;
        }
    }
    if (ialpha < 0) ialpha = n_in - 1;

    const void*  a     = d_in[ia];
    const void*  b     = d_in[ib];
    const float* alpha = reinterpret_cast<const float*>(d_in[ialpha]);
    float*       out   = reinterpret_cast<float*>(d_out);

    probe_dtype_kernel<<<1, 256>>>(reinterpret_cast<const uint32_t*>(a));
    pack_kernel<<<WORDS / 256, 256>>>(a, b);

    dim3 grid(NN / 128, MM / 128, BB);   // (16, 16, 64)
    bmm_mma_kernel<<<grid, 256>>>(alpha, out);
}

// round 6
// speedup vs baseline: 2.6595x; 1.0057x over previous
#include <cuda_runtime.h>
#include <cstdint>

// Problem constants (fixed by the reference)
#define BB   64
#define MM   2048
#define NN   2048
#define KK   64                      // K in logical int8 elements
#define KW   16                      // K in packed 32-bit words
#define WORDS (BB * MM * KK / 4)     // packed words per tensor = 2,097,152

#define ROWB 20                      // smem tile row pitch in words (80B, ldmatrix conflict-free)
#define EPS  36                      // epilogue staging row pitch in floats (conflict-free LDS.128)

// 1 if the harness promoted int8 inputs to int32 (one int32 per element)
__device__ int g_inputs_are_i32;

// Packed int8 scratch (static device arrays — allowed)
__device__ uint32_t A_pk[WORDS];     // 8.4 MB
__device__ uint32_t B_pk[WORDS];     // 8.4 MB

__device__ __forceinline__ uint32_t pack4(int4 v)
{
    return (uint32_t)(v.x & 0xff)
         | ((uint32_t)(v.y & 0xff) << 8)
         | ((uint32_t)(v.z & 0xff) << 16)
         | ((uint32_t)(v.w)        << 24);
}

// ---------------------------------------------------------------------------
// Parallel dtype probe
// ---------------------------------------------------------------------------
__global__ void probe_dtype_kernel(const uint32_t* __restrict__ a)
{
    int ok = 1;
    #pragma unroll
    for (int r = 0; r < 8; r++) {
        uint32_t v = a[threadIdx.x + r * 256];
        uint32_t hi = v >> 8;
        uint32_t expect = (v & 0x80u) ? 0x00FFFFFFu : 0x00000000u;
        if (hi != expect) ok = 0;
    }
    int all = __syncthreads_and(ok);
    if (threadIdx.x == 0) g_inputs_are_i32 = all;
}

// ---------------------------------------------------------------------------
// Pack: int32-promoted -> packed int8 words (or plain copy if already packed)
// ---------------------------------------------------------------------------
__global__ __launch_bounds__(256)
void pack_kernel(const void* __restrict__ srcA, const void* __restrict__ srcB)
{
    const int i = blockIdx.x * blockDim.x + threadIdx.x;   // word index
    if (i >= WORDS) return;
    if (g_inputs_are_i32) {
        A_pk[i] = pack4(reinterpret_cast<const int4*>(srcA)[i]);
        B_pk[i] = pack4(reinterpret_cast<const int4*>(srcB)[i]);
    } else {
        A_pk[i] = reinterpret_cast<const uint32_t*>(srcA)[i];
        B_pk[i] = reinterpret_cast<const uint32_t*>(srcB)[i];
    }
}

// ---------------------------------------------------------------------------
// Tensor-core GEMM: mma.sync.m16n8k32.s8, CTA 128x128, 8 warps, warp 64x32.
// ldmatrix-fed fragments; smem-staged epilogue for fully coalesced STG.128.
// ---------------------------------------------------------------------------
__global__ __launch_bounds__(256, 2)
void bmm_mma_kernel(const float* __restrict__ alpha_p, float* __restrict__ out)
{
    // Unified smem: operand tiles during mainloop, epilogue staging afterwards.
    // As: words [0, 2560)   Bs: words [2560, 5120)   staging: words [0, 4608)
    __shared__ uint32_t smem_buf[5120];          // 20 KB
    uint32_t* As = smem_buf;
    uint32_t* Bs = smem_buf + 128 * ROWB;

    const int bz     = blockIdx.z;
    const int tile_m = blockIdx.y * 128;
    const int tile_n = blockIdx.x * 128;
    const int tid    = threadIdx.x;

    // ---- Global -> shared: 128 rows x 64B per operand ----
    {
        const uint32_t* __restrict__ Aw = A_pk + (size_t)bz * MM * KW + (size_t)tile_m * KW;
        const uint32_t* __restrict__ Bw = B_pk + (size_t)bz * NN * KW + (size_t)tile_n * KW;
        #pragma unroll
        for (int p = 0; p < 2; p++) {
            const int idx = tid + p * 256;     // 0..511
            const int row = idx >> 2;
            const int q   = idx & 3;           // 16B chunk within row
            uint4 va = *reinterpret_cast<const uint4*>(Aw + (size_t)row * KW + q * 4);
            uint4 vb = *reinterpret_cast<const uint4*>(Bw + (size_t)row * KW + q * 4);
            *reinterpret_cast<uint4*>(&As[row * ROWB + q * 4]) = va;
            *reinterpret_cast<uint4*>(&Bs[row * ROWB + q * 4]) = vb;
        }
    }
    __syncthreads();

    const int wid  = tid >> 5;
    const int lane = tid & 31;
    const int g    = lane >> 2;      // row/col group 0..7
    const int t    = lane & 3;       // k-word lane 0..3

    const int wm = wid >> 2;         // 0..1 -> m offset (x64)
    const int wn = wid & 3;          // 0..3 -> n offset (x32)

    // ---- ldmatrix lane addresses ----
    const uint32_t As_u32 = (uint32_t)__cvta_generic_to_shared(As);
    const uint32_t Bs_u32 = (uint32_t)__cvta_generic_to_shared(Bs);

    const int arow = ((lane >> 3) & 1) * 8 + (lane & 7);
    const int akof = (lane >> 4) * 16;
    uint32_t a_addr[4];
    #pragma unroll
    for (int mi = 0; mi < 4; mi++)
        a_addr[mi] = As_u32 + (uint32_t)((wm * 64 + mi * 16 + arow) * (ROWB * 4) + akof);

    const int brow = ((lane >> 4) & 1) * 8 + (lane & 7);
    const int bkof = ((lane >> 3) & 1) * 16;
    uint32_t b_addr[2];
    #pragma unroll
    for (int p = 0; p < 2; p++)
        b_addr[p] = Bs_u32 + (uint32_t)((wn * 32 + p * 16 + brow) * (ROWB * 4) + bkof);

    int c[4][4][4] = {};             // [m16 tile][n8 tile][frag reg]

    #pragma unroll
    for (int s = 0; s < 2; s++) {    // k-step
        uint32_t a[4][4];
        #pragma unroll
        for (int mi = 0; mi < 4; mi++)
            asm volatile("ldmatrix.sync.aligned.m8n8.x4.shared.b16 {%0,%1,%2,%3}, [%4];\n"
                         : "=r"(a[mi][0]), "=r"(a[mi][1]), "=r"(a[mi][2]), "=r"(a[mi][3])
                         : "r"(a_addr[mi] + s * 32));

        uint32_t b[4][2];
        #pragma unroll
        for (int p = 0; p < 2; p++)
            asm volatile("ldmatrix.sync.aligned.m8n8.x4.shared.b16 {%0,%1,%2,%3}, [%4];\n"
                         : "=r"(b[2 * p][0]), "=r"(b[2 * p][1]),
                           "=r"(b[2 * p + 1][0]), "=r"(b[2 * p + 1][1])
                         : "r"(b_addr[p] + s * 32));

        #pragma unroll
        for (int mi = 0; mi < 4; mi++)
            #pragma unroll
            for (int nj = 0; nj < 4; nj++)
                asm volatile(
                    "mma.sync.aligned.m16n8k32.row.col.s32.s8.s8.s32 "
                    "{%0,%1,%2,%3}, {%4,%5,%6,%7}, {%8,%9}, {%0,%1,%2,%3};\n"
                    : "+r"(c[mi][nj][0]), "+r"(c[mi][nj][1]),
                      "+r"(c[mi][nj][2]), "+r"(c[mi][nj][3])
                    : "r"(a[mi][0]), "r"(a[mi][1]), "r"(a[mi][2]), "r"(a[mi][3]),
                      "r"(b[nj][0]), "r"(b[nj][1]));
    }

    // ---- Smem-staged epilogue: alpha * s32 -> f32, coalesced STG.128 ----
    const float alpha = __ldg(alpha_p);
    const int m_base = tile_m + wm * 64;
    const int n_base = tile_n + wn * 32;
    float* __restrict__ obase = out + (size_t)bz * MM * NN + n_base;

    __syncthreads();                 // operand tiles dead; reuse smem for staging

    float* stage = reinterpret_cast<float*>(smem_buf) + wid * (16 * EPS);
    const int lrow = lane >> 3;      // 0..3: row within 4-row store group
    const int lcol = (lane & 7) * 4; // 0..28: float4 column

    #pragma unroll
    for (int mi = 0; mi < 4; mi++) {
        // scatter c-frags into staging (rows g / g+8, cols nj*8 + 2t)
        #pragma unroll
        for (int nj = 0; nj < 4; nj++) {
            const int col = nj * 8 + 2 * t;
            float2 v0, v1;
            v0.x = alpha * (float)c[mi][nj][0];
            v0.y = alpha * (float)c[mi][nj][1];
            v1.x = alpha * (float)c[mi][nj][2];
            v1.y = alpha * (float)c[mi][nj][3];
            *reinterpret_cast<float2*>(stage + g * EPS + col)       = v0;
            *reinterpret_cast<float2*>(stage + (g + 8) * EPS + col) = v1;
        }
        __syncwarp();
        // coalesced readback + store: 4 rows per STG.128 instruction
        #pragma unroll
        for (int j = 0; j < 4; j++) {
            const int r = j * 4 + lrow;        // 0..15
            float4 v = *reinterpret_cast<const float4*>(stage + r * EPS + lcol);
            *reinterpret_cast<float4*>(obase + (size_t)(m_base + mi * 16 + r) * NN + lcol) = v;
        }
        __syncwarp();
    }
}

extern "C" void kernel_launch(void* const* d_in, const int* in_sizes, int n_in,
                              void* d_out, int out_size)
{
    // alpha is the unique 1-element input; the two big tensors are a then b.
    int ia = -1, ib = -1, ialpha = -1;
    for (int i = 0; i < n_in; i++) {
        if (in_sizes[i] == 1) {
            if (ialpha < 0) ialpha = i;
        } else if (ia < 0) {
            ia = i;
        } else if (ib < 0) {
            ib = i;
        }
    }
    if (ialpha < 0) ialpha = n_in - 1;

    const void*  a     = d_in[ia];
    const void*  b     = d_in[ib];
    const float* alpha = reinterpret_cast<const float*>(d_in[ialpha]);
    float*       out   = reinterpret_cast<float*>(d_out);

    probe_dtype_kernel<<<1, 256>>>(reinterpret_cast<const uint32_t*>(a));
    pack_kernel<<<WORDS / 256, 256>>>(a, b);

    dim3 grid(NN / 128, MM / 128, BB);   // (16, 16, 64)
    bmm_mma_kernel<<<grid, 256>>>(alpha, out);
}

// round 7
// speedup vs baseline: 2.8112x; 1.0570x over previous
#include <cuda_runtime.h>
#include <cstdint>

// Problem constants (fixed by the reference)
#define BB   64
#define MM   2048
#define NN   2048
#define KK   64                      // K in logical int8 elements
#define KW   16                      // K in packed 32-bit words
#define WORDS (BB * MM * KK / 4)     // packed words per tensor = 2,097,152

#define ROWB 20                      // smem tile row pitch in words (80B, ldmatrix conflict-free)

// Packed int8 scratch (static device arrays — allowed)
__device__ uint32_t A_pk[WORDS];     // 8.4 MB
__device__ uint32_t B_pk[WORDS];     // 8.4 MB

__device__ __forceinline__ uint32_t pack4(int4 v)
{
    return (uint32_t)(v.x & 0xff)
         | ((uint32_t)(v.y & 0xff) << 8)
         | ((uint32_t)(v.z & 0xff) << 16)
         | ((uint32_t)(v.w)        << 24);
}

// ---------------------------------------------------------------------------
// Fused probe + pack. Each block independently probes the first 256 words of
// `a`: int32-promoted int8 words have bytes 1..3 equal to the sign extension
// of byte 0 (false-positive prob for genuine packed data ~ (1.2e-7)^256 = 0).
// Then packs 4 words per thread.
// ---------------------------------------------------------------------------
__global__ __launch_bounds__(256)
void pack_kernel(const void* __restrict__ srcA, const void* __restrict__ srcB)
{
    // Per-block dtype probe (uniform result across all blocks)
    uint32_t v = reinterpret_cast<const uint32_t*>(srcA)[threadIdx.x];
    uint32_t expect = (v & 0x80u) ? 0x00FFFFFFu : 0x00000000u;
    int is_i32 = __syncthreads_and((v >> 8) == expect);

    const int base = (blockIdx.x * blockDim.x + threadIdx.x) * 4;  // word index
    if (base >= WORDS) return;

    if (is_i32) {
        const int4* A4 = reinterpret_cast<const int4*>(srcA) + base;
        const int4* B4 = reinterpret_cast<const int4*>(srcB) + base;
        uint4 oa, ob;
        oa.x = pack4(A4[0]); oa.y = pack4(A4[1]); oa.z = pack4(A4[2]); oa.w = pack4(A4[3]);
        ob.x = pack4(B4[0]); ob.y = pack4(B4[1]); ob.z = pack4(B4[2]); ob.w = pack4(B4[3]);
        *reinterpret_cast<uint4*>(&A_pk[base]) = oa;
        *reinterpret_cast<uint4*>(&B_pk[base]) = ob;
    } else {
        *reinterpret_cast<uint4*>(&A_pk[base]) =
            reinterpret_cast<const uint4*>(srcA)[base >> 2];
        *reinterpret_cast<uint4*>(&B_pk[base]) =
            reinterpret_cast<const uint4*>(srcB)[base >> 2];
    }
}

// ---------------------------------------------------------------------------
// Tensor-core GEMM: mma.sync.m16n8k32.s8, CTA 128x128, 8 warps, warp 64x32.
// ldmatrix-fed fragments; butterfly-shuffle epilogue -> direct STG.128.
// ---------------------------------------------------------------------------
__global__ __launch_bounds__(256, 2)
void bmm_mma_kernel(const float* __restrict__ alpha_p, float* __restrict__ out)
{
    __shared__ uint32_t As[128 * ROWB];   // 10 KB
    __shared__ uint32_t Bs[128 * ROWB];   // 10 KB

    const int bz     = blockIdx.z;
    const int tile_m = blockIdx.y * 128;
    const int tile_n = blockIdx.x * 128;
    const int tid    = threadIdx.x;

    // ---- Global -> shared: 128 rows x 64B per operand ----
    {
        const uint32_t* __restrict__ Aw = A_pk + (size_t)bz * MM * KW + (size_t)tile_m * KW;
        const uint32_t* __restrict__ Bw = B_pk + (size_t)bz * NN * KW + (size_t)tile_n * KW;
        #pragma unroll
        for (int p = 0; p < 2; p++) {
            const int idx = tid + p * 256;     // 0..511
            const int row = idx >> 2;
            const int q   = idx & 3;           // 16B chunk within row
            uint4 va = *reinterpret_cast<const uint4*>(Aw + (size_t)row * KW + q * 4);
            uint4 vb = *reinterpret_cast<const uint4*>(Bw + (size_t)row * KW + q * 4);
            *reinterpret_cast<uint4*>(&As[row * ROWB + q * 4]) = va;
            *reinterpret_cast<uint4*>(&Bs[row * ROWB + q * 4]) = vb;
        }
    }
    __syncthreads();

    const int wid  = tid >> 5;
    const int lane = tid & 31;
    const int g    = lane >> 2;      // row/col group 0..7
    const int t    = lane & 3;       // k-word lane 0..3

    const int wm = wid >> 2;         // 0..1 -> m offset (x64)
    const int wn = wid & 3;          // 0..3 -> n offset (x32)

    // ---- ldmatrix lane addresses ----
    const uint32_t As_u32 = (uint32_t)__cvta_generic_to_shared(As);
    const uint32_t Bs_u32 = (uint32_t)__cvta_generic_to_shared(Bs);

    const int arow = ((lane >> 3) & 1) * 8 + (lane & 7);
    const int akof = (lane >> 4) * 16;
    uint32_t a_addr[4];
    #pragma unroll
    for (int mi = 0; mi < 4; mi++)
        a_addr[mi] = As_u32 + (uint32_t)((wm * 64 + mi * 16 + arow) * (ROWB * 4) + akof);

    const int brow = ((lane >> 4) & 1) * 8 + (lane & 7);
    const int bkof = ((lane >> 3) & 1) * 16;
    uint32_t b_addr[2];
    #pragma unroll
    for (int p = 0; p < 2; p++)
        b_addr[p] = Bs_u32 + (uint32_t)((wn * 32 + p * 16 + brow) * (ROWB * 4) + bkof);

    int c[4][4][4] = {};             // [m16 tile][n8 tile][frag reg]

    #pragma unroll
    for (int s = 0; s < 2; s++) {    // k-step
        uint32_t a[4][4];
        #pragma unroll
        for (int mi = 0; mi < 4; mi++)
            asm volatile("ldmatrix.sync.aligned.m8n8.x4.shared.b16 {%0,%1,%2,%3}, [%4];\n"
                         : "=r"(a[mi][0]), "=r"(a[mi][1]), "=r"(a[mi][2]), "=r"(a[mi][3])
                         : "r"(a_addr[mi] + s * 32));

        uint32_t b[4][2];
        #pragma unroll
        for (int p = 0; p < 2; p++)
            asm volatile("ldmatrix.sync.aligned.m8n8.x4.shared.b16 {%0,%1,%2,%3}, [%4];\n"
                         : "=r"(b[2 * p][0]), "=r"(b[2 * p][1]),
                           "=r"(b[2 * p + 1][0]), "=r"(b[2 * p + 1][1])
                         : "r"(b_addr[p] + s * 32));

        #pragma unroll
        for (int mi = 0; mi < 4; mi++)
            #pragma unroll
            for (int nj = 0; nj < 4; nj++)
                asm volatile(
                    "mma.sync.aligned.m16n8k32.row.col.s32.s8.s8.s32 "
                    "{%0,%1,%2,%3}, {%4,%5,%6,%7}, {%8,%9}, {%0,%1,%2,%3};\n"
                    : "+r"(c[mi][nj][0]), "+r"(c[mi][nj][1]),
                      "+r"(c[mi][nj][2]), "+r"(c[mi][nj][3])
                    : "r"(a[mi][0]), "r"(a[mi][1]), "r"(a[mi][2]), "r"(a[mi][3]),
                      "r"(b[nj][0]), "r"(b[nj][1]));
    }

    // ---- Butterfly epilogue: merge adjacent-nj float2s into float4s ----
    // Lane decomposition: g = lane>>2, t = lane&3 = 2u+e.
    // After shfl-xor(1): lane (g,u,e) owns float4s at rows {g, g+8} (+16*mi),
    // cols n_base + 16p + 8e + 4u, for p in {0,1}.
    const float alpha = __ldg(alpha_p);
    const int u = t >> 1;
    const int e = t & 1;
    const int m_base = tile_m + wm * 64;
    const int n_base = tile_n + wn * 32;
    float* __restrict__ obase = out + (size_t)bz * MM * NN;

    #pragma unroll
    for (int mi = 0; mi < 4; mi++) {
        float f[4][4];
        #pragma unroll
        for (int nj = 0; nj < 4; nj++)
            #pragma unroll
            for (int r = 0; r < 4; r++)
                f[nj][r] = alpha * (float)c[mi][nj][r];

        const int row_lo = m_base + mi * 16 + g;

        #pragma unroll
        for (int p = 0; p < 2; p++) {
            const int njA = 2 * p;       // cols 16p + 0..7
            const int njB = 2 * p + 1;   // cols 16p + 8..15

            // e==0 sends its njB half; e==1 sends its njA half
            float s0 = e ? f[njA][0] : f[njB][0];
            float s1 = e ? f[njA][1] : f[njB][1];
            float s2 = e ? f[njA][2] : f[njB][2];
            float s3 = e ? f[njA][3] : f[njB][3];
            float r0 = __shfl_xor_sync(0xFFFFFFFFu, s0, 1);
            float r1 = __shfl_xor_sync(0xFFFFFFFFu, s1, 1);
            float r2 = __shfl_xor_sync(0xFFFFFFFFu, s2, 1);
            float r3 = __shfl_xor_sync(0xFFFFFFFFu, s3, 1);

            float4 vlo, vhi;
            if (e == 0) {   // own njA cols {4u,4u+1} + partner's njA {4u+2,4u+3}
                vlo = make_float4(f[njA][0], f[njA][1], r0, r1);
                vhi = make_float4(f[njA][2], f[njA][3], r2, r3);
            } else {        // partner's njB {4u,4u+1} + own njB {4u+2,4u+3}
                vlo = make_float4(r0, r1, f[njB][0], f[njB][1]);
                vhi = make_float4(r2, r3, f[njB][2], f[njB][3]);
            }

            const int col = n_base + 16 * p + 8 * e + 4 * u;
            *reinterpret_cast<float4*>(obase + (size_t)row_lo * NN + col)       = vlo;
            *reinterpret_cast<float4*>(obase + (size_t)(row_lo + 8) * NN + col) = vhi;
        }
    }
}

extern "C" void kernel_launch(void* const* d_in, const int* in_sizes, int n_in,
                              void* d_out, int out_size)
{
    // alpha is the unique 1-element input; the two big tensors are a then b.
    int ia = -1, ib = -1, ialpha = -1;
    for (int i = 0; i < n_in; i++) {
        if (in_sizes[i] == 1) {
            if (ialpha < 0) ialpha = i;
        } else if (ia < 0) {
            ia = i;
        } else if (ib < 0) {
            ib = i;
        }
    }
    if (ialpha < 0) ialpha = n_in - 1;

    const void*  a     = d_in[ia];
    const void*  b     = d_in[ib];
    const float* alpha = reinterpret_cast<const float*>(d_in[ialpha]);
    float*       out   = reinterpret_cast<float*>(d_out);

    pack_kernel<<<WORDS / (256 * 4), 256>>>(a, b);

    dim3 grid(NN / 128, MM / 128, BB);   // (16, 16, 64)
    bmm_mma_kernel<<<grid, 256>>>(alpha, out);
}